// round 16
// baseline (speedup 1.0000x reference)
#include <cuda_runtime.h>
#include <cstdint>

// Dynamic 5x5 per-pixel convolution + leaky_relu(0.2), replicate padding.
// x:      (N, C, H, W)    f32  -> 8 MB   (staged per CTA via cp.async.16B)
// kernel: (N, C*25, H, W) f32  -> 200 MB (dominant HBM stream, read once)
// out:    (N, C, H, W)    f32  -> 8 MB
//
// R15 = exact revert to R8, the verified best (35.3us, DRAM 76.7%).
// Structure: 512 CTAs x 256 thr (single wave), 16-row strips staged once via
// vectorized cp.async (interior 16B, edges scalar), ONE barrier, row-0 taps
// prefetched under the stage wait, in-row double-buffered tap stream
// (5 LDG.128 in flight), __stcs streaming stores.
// R6/R7/R10/R12 restructures (finer grid, flattening, parity handoff,
// load hoisting) all regressed; ptxas's schedule of this form is the optimum.

#define W_DIM 256
#define H_DIM 256
#define HW (W_DIM * H_DIM)
#define KS 5
#define PAD 2
#define ROWS_PER_CTA 16
#define ROWS_PER_THREAD 4
#define TILE_ROWS (ROWS_PER_CTA + 2 * PAD)   // 20
#define SROW 272                             // 16B-aligned row stride
#define COL0 4                               // smem col = gx + COL0
#define NTHREADS 256

__device__ __forceinline__ void cp_async16(uint32_t smem_addr, const float* gptr) {
    asm volatile("cp.async.cg.shared.global [%0], [%1], 16;"
                 :: "r"(smem_addr), "l"(gptr));
}
__device__ __forceinline__ void cp_async4(uint32_t smem_addr, const float* gptr) {
    asm volatile("cp.async.ca.shared.global [%0], [%1], 4;"
                 :: "r"(smem_addr), "l"(gptr));
}

__global__ __launch_bounds__(NTHREADS, 4)
void dynconv5x5_kernel(const float* __restrict__ x,
                       const float* __restrict__ kern,
                       float* __restrict__ out)
{
    __shared__ float xs[TILE_ROWS][SROW];

    const int nc    = blockIdx.x >> 4;                   // plane index (0..31)
    const int hbase = (blockIdx.x & 15) * ROWS_PER_CTA;  // strip start row
    const int tx    = threadIdx.x;                       // 0..63 -> 4-px group
    const int ty    = threadIdx.y;                       // 0..3
    const int tid   = ty * 64 + tx;
    const int wbase = tx * 4;

    const float* xp    = x    + (size_t)nc * HW;
    const float* kpl   = kern + (size_t)nc * 25 * HW;
    float*       outpl = out  + (size_t)nc * HW;

    uint32_t xs_base;
    asm("{ .reg .u64 t; cvta.to.shared.u64 t, %1; cvt.u32.u64 %0, t; }"
        : "=r"(xs_base) : "l"(&xs[0][0]));

    // ---- stage interior: 20 rows x 64 aligned float4 groups (16B cp.async) ----
    for (int i = tid; i < TILE_ROWS * (W_DIM / 4); i += NTHREADS) {
        int r = i >> 6;                 // row 0..19
        int g = i & 63;                 // float4 group, gx = 4g
        int gy = hbase + r - PAD;
        gy = gy < 0 ? 0 : (gy > H_DIM - 1 ? H_DIM - 1 : gy);
        cp_async16(xs_base + (uint32_t)(r * SROW + COL0 + 4 * g) * 4u,
                   xp + gy * W_DIM + 4 * g);
    }
    // ---- stage edges: 4 clamped scalars per row (cols 2,3 -> x[,0]; 260,261 -> x[,255]) ----
    for (int i = tid; i < TILE_ROWS * 4; i += NTHREADS) {
        int r = i >> 2;
        int e = i & 3;
        int gy = hbase + r - PAD;
        gy = gy < 0 ? 0 : (gy > H_DIM - 1 ? H_DIM - 1 : gy);
        int col = (e < 2) ? (2 + e) : (258 + e);          // 2,3,260,261
        int gx  = (e < 2) ? 0 : (W_DIM - 1);
        cp_async4(xs_base + (uint32_t)(r * SROW + col) * 4u,
                  xp + gy * W_DIM + gx);
    }
    asm volatile("cp.async.commit_group;");

    // ---- prefetch row-0 taps (rr=0) BEFORE the stage wait ----
    float4 kv[2][KS];
    {
        const int h0 = hbase + ty;
        const float* kb0 = kpl + (size_t)h0 * W_DIM + wbase;
        #pragma unroll
        for (int k2 = 0; k2 < KS; k2++)
            kv[0][k2] = __ldcs((const float4*)(kb0 + (size_t)k2 * HW));
    }

    asm volatile("cp.async.wait_group 0;");
    __syncthreads();   // the ONLY barrier

    // Each thread: rows hbase + ty + 4*rr, rr = 0..3
    #pragma unroll 1
    for (int rr = 0; rr < ROWS_PER_THREAD; rr++) {
        const int hloc = ty + rr * 4;            // row within strip (0..15)
        const int h    = hbase + hloc;           // global row
        const float* kbase = kpl + (size_t)h * W_DIM + wbase;

        if (rr > 0) {   // rr=0's kv[0] was preloaded under the stage wait
            #pragma unroll
            for (int k2 = 0; k2 < KS; k2++)
                kv[0][k2] = __ldcs((const float4*)(kbase + (size_t)k2 * HW));
        }

        float acc0 = 0.f, acc1 = 0.f, acc2 = 0.f, acc3 = 0.f;

        #pragma unroll
        for (int k1 = 0; k1 < KS; k1++) {
            const int cur = k1 & 1;
            if (k1 < KS - 1) {
                #pragma unroll
                for (int k2 = 0; k2 < KS; k2++)
                    kv[cur ^ 1][k2] =
                        __ldcs((const float4*)(kbase + (size_t)((k1 + 1) * KS + k2) * HW));
            }

            // 12-float window (3 aligned LDS.128); cols wbase..wbase+11,
            // i.e. gx = wbase-4 .. wbase+7; taps use gx wbase-2+k2+i -> arr[k2+2+i]
            float4 a = *(const float4*)&xs[hloc + k1][wbase];
            float4 b = *(const float4*)&xs[hloc + k1][wbase + 4];
            float4 c = *(const float4*)&xs[hloc + k1][wbase + 8];
            float arr[12] = {a.x, a.y, a.z, a.w, b.x, b.y, b.z, b.w,
                             c.x, c.y, c.z, c.w};

            #pragma unroll
            for (int k2 = 0; k2 < KS; k2++) {
                float4 c4 = kv[cur][k2];
                acc0 = fmaf(c4.x, arr[k2 + 2], acc0);
                acc1 = fmaf(c4.y, arr[k2 + 3], acc1);
                acc2 = fmaf(c4.z, arr[k2 + 4], acc2);
                acc3 = fmaf(c4.w, arr[k2 + 5], acc3);
            }
        }

        // leaky_relu(0.2) + streaming store of this row's 4 px
        acc0 = acc0 >= 0.f ? acc0 : 0.2f * acc0;
        acc1 = acc1 >= 0.f ? acc1 : 0.2f * acc1;
        acc2 = acc2 >= 0.f ? acc2 : 0.2f * acc2;
        acc3 = acc3 >= 0.f ? acc3 : 0.2f * acc3;

        __stcs((float4*)(outpl + (size_t)h * W_DIM + wbase),
               make_float4(acc0, acc1, acc2, acc3));
    }
}

extern "C" void kernel_launch(void* const* d_in, const int* in_sizes, int n_in,
                              void* d_out, int out_size)
{
    const float* x    = (const float*)d_in[0];
    const float* kern = (const float*)d_in[1];
    float* out        = (float*)d_out;

    const int NC = in_sizes[0] / HW;              // 32 for (4,8,256,256)

    dim3 block(64, 4);
    dim3 grid(NC * (H_DIM / ROWS_PER_CTA));       // 512 CTAs, single wave
    dynconv5x5_kernel<<<grid, block>>>(x, kern, out);
}